// round 16
// baseline (speedup 1.0000x reference)
#include <cuda_runtime.h>
#include <cuda_bf16.h>
#include <stdint.h>
#include <math.h>

#define N_NODES 20000
#define E_EDGES 200000
#define ET_EDGES 40000
#define DIN 8
#define HDIM 128
#define NEA 7
#define HC 896
#define HLDIM 128
#define OUTD 4

typedef unsigned long long u64;
typedef unsigned int u32;
typedef __nv_bfloat16 bf16;

// ---------------- scratch ----------------
static __device__ float g_ew[E_EDGES];
static __device__ float g_dis[8 * N_NODES];
static __device__ float g_hw[(size_t)N_NODES * HC];
static __device__ float g_hw128[(size_t)N_NODES * HDIM];
static __device__ float g_UV[(size_t)N_NODES * 256];
static __device__ float g_Hb_f32[(size_t)2 * ET_EDGES * HLDIM];
static __device__ float g_T[(size_t)2 * ET_EDGES * OUTD];
static __device__ bf16 g_x1h[(size_t)N_NODES * HC];
static __device__ bf16 g_x1l[(size_t)N_NODES * HC];
static __device__ bf16 g_x2h[(size_t)N_NODES * HDIM];
static __device__ bf16 g_x2l[(size_t)N_NODES * HDIM];
static __device__ bf16 g_x3h[(size_t)N_NODES * HC];
static __device__ bf16 g_x3l[(size_t)N_NODES * HC];
static __device__ bf16 g_x4h[(size_t)N_NODES * HC];
static __device__ bf16 g_x4l[(size_t)N_NODES * HC];
static __device__ bf16 g_Hah[(size_t)2 * ET_EDGES * HLDIM];
static __device__ bf16 g_Hal[(size_t)2 * ET_EDGES * HLDIM];
static __device__ bf16 g_Hbh[(size_t)2 * ET_EDGES * HLDIM];
static __device__ bf16 g_Hbl[(size_t)2 * ET_EDGES * HLDIM];
static __device__ bf16 g_B1h[HDIM * HC];
static __device__ bf16 g_B1l[HDIM * HC];
static __device__ bf16 g_B2h[HC * HDIM];
static __device__ bf16 g_B2l[HC * HDIM];
static __device__ bf16 g_B3h[(size_t)HC * HC];
static __device__ bf16 g_B3l[(size_t)HC * HC];
static __device__ bf16 g_Buvh[256 * HC];
static __device__ bf16 g_Buvl[256 * HC];
static __device__ bf16 g_Blhh[3 * HLDIM * HLDIM];
static __device__ bf16 g_Blhl[3 * HLDIM * HLDIM];
static __device__ int g_cnt[N_NODES];
static __device__ int g_cursor[N_NODES];
static __device__ int g_rowptr[N_NODES + 1];
static __device__ int g_csr_r[E_EDGES];
static __device__ int g_csr_e[E_EDGES];

// ---------------- bf16 split helpers ----------------
__device__ __forceinline__ void split1(float v, bf16* ph, bf16* pl) {
    bf16 h = __float2bfloat16(v);
    *ph = h;
    *pl = __float2bfloat16(v - __bfloat162float(h));
}
__device__ __forceinline__ void split_store4(bf16* ph, bf16* pl, float4 v) {
    bf16 h0 = __float2bfloat16(v.x);
    bf16 h1 = __float2bfloat16(v.y);
    bf16 h2 = __float2bfloat16(v.z);
    bf16 h3 = __float2bfloat16(v.w);
    bf16 l0 = __float2bfloat16(v.x - __bfloat162float(h0));
    bf16 l1 = __float2bfloat16(v.y - __bfloat162float(h1));
    bf16 l2 = __float2bfloat16(v.z - __bfloat162float(h2));
    bf16 l3 = __float2bfloat16(v.w - __bfloat162float(h3));
    __nv_bfloat162* H = reinterpret_cast<__nv_bfloat162*>(ph);
    __nv_bfloat162* L = reinterpret_cast<__nv_bfloat162*>(pl);
    H[0] = __halves2bfloat162(h0, h1);
    H[1] = __halves2bfloat162(h2, h3);
    L[0] = __halves2bfloat162(l0, l1);
    L[1] = __halves2bfloat162(l2, l3);
}
__device__ __forceinline__ void split_store2(bf16* ph, bf16* pl, float x, float y) {
    bf16 hx = __float2bfloat16(x);
    bf16 hy = __float2bfloat16(y);
    bf16 lx = __float2bfloat16(x - __bfloat162float(hx));
    bf16 ly = __float2bfloat16(y - __bfloat162float(hy));
    *reinterpret_cast<__nv_bfloat162*>(ph) = __halves2bfloat162(hx, hy);
    *reinterpret_cast<__nv_bfloat162*>(pl) = __halves2bfloat162(lx, ly);
}

__device__ __forceinline__ u32 smem_u32(const void* p) {
    u32 a;
    asm("{ .reg .u64 t; cvta.to.shared.u64 t, %1; cvt.u32.u64 %0, t; }" : "=r"(a) : "l"(p));
    return a;
}

// ---------------- bf16 mma.sync GEMM with cp.async pipeline ----------------
#define GBK 32
#define ASTR 40
#define TSZ (128 * ASTR)
#define MMA_SMEM (2 * 4 * TSZ * 2)

#define MMA_BF16(d, a, b0v, b1v) \
    asm volatile("mma.sync.aligned.m16n8k16.row.col.f32.bf16.bf16.f32 " \
        "{%0,%1,%2,%3}, {%4,%5,%6,%7}, {%8,%9}, {%0,%1,%2,%3};" \
        : "+f"((d)[0]), "+f"((d)[1]), "+f"((d)[2]), "+f"((d)[3]) \
        : "r"((a)[0]), "r"((a)[1]), "r"((a)[2]), "r"((a)[3]), "r"(b0v), "r"(b1v))

#define CP_ASYNC16(dst_u32, src_ptr, nbytes) \
    asm volatile("cp.async.cg.shared.global [%0], [%1], 16, %2;" \
                 :: "r"(dst_u32), "l"(src_ptr), "r"(nbytes) : "memory")
#define CP_COMMIT() asm volatile("cp.async.commit_group;" ::: "memory")
#define CP_WAIT1()  asm volatile("cp.async.wait_group 1;" ::: "memory")
#define CP_WAIT0()  asm volatile("cp.async.wait_group 0;" ::: "memory")

__device__ __forceinline__ void gt_load_async(
    u32 smbase, int buf, int kb,
    const bf16* Ah, const bf16* Al, const bf16* Bh, const bf16* Bl,
    int rowBase, int colBase, int M, int K, int r0, int r1, int kv)
{
    u32 base = smbase + (u32)buf * 4 * TSZ * 2;
    u32 d00 = base + (u32)(0 * TSZ + r0 * ASTR + kv) * 2;
    u32 d01 = base + (u32)(0 * TSZ + r1 * ASTR + kv) * 2;
    u32 d10 = base + (u32)(1 * TSZ + r0 * ASTR + kv) * 2;
    u32 d11 = base + (u32)(1 * TSZ + r1 * ASTR + kv) * 2;
    u32 d20 = base + (u32)(2 * TSZ + r0 * ASTR + kv) * 2;
    u32 d21 = base + (u32)(2 * TSZ + r1 * ASTR + kv) * 2;
    u32 d30 = base + (u32)(3 * TSZ + r0 * ASTR + kv) * 2;
    u32 d31 = base + (u32)(3 * TSZ + r1 * ASTR + kv) * 2;
    size_t a0 = (size_t)(rowBase + r0) * K + kb + kv;
    size_t a1 = (size_t)(rowBase + r1) * K + kb + kv;
    int n0 = ((rowBase + r0) < M) ? 16 : 0;
    int n1 = ((rowBase + r1) < M) ? 16 : 0;
    CP_ASYNC16(d00, Ah + a0, n0);
    CP_ASYNC16(d01, Ah + a1, n1);
    CP_ASYNC16(d10, Al + a0, n0);
    CP_ASYNC16(d11, Al + a1, n1);
    size_t b0 = (size_t)(colBase + r0) * K + kb + kv;
    size_t b1 = (size_t)(colBase + r1) * K + kb + kv;
    CP_ASYNC16(d20, Bh + b0, 16);
    CP_ASYNC16(d21, Bh + b1, 16);
    CP_ASYNC16(d30, Bl + b0, 16);
    CP_ASYNC16(d31, Bl + b1, 16);
}

__global__ __launch_bounds__(256)
void gemm_mma_kernel(
    const bf16* __restrict__ Ah, const bf16* __restrict__ Al,
    const bf16* __restrict__ Bh, const bf16* __restrict__ Bl,
    float* __restrict__ C, bf16* __restrict__ CH, bf16* __restrict__ CL,
    int M, int K, int Nc, const float* __restrict__ bias, int flags)
{
    extern __shared__ bf16 sm[];
    const u32 smb = smem_u32(sm);
    const int tid = threadIdx.x;
    const int wid = tid >> 5;
    const int lane = tid & 31;
    const int rowBase = blockIdx.y * 128;
    const int colBase = blockIdx.x * 128;
    const int wRow = (wid & 3) * 32;
    const int wCol = (wid >> 2) * 64;
    const int ar = lane >> 2;
    const int ac = (lane & 3) << 1;

    const int lr0 = tid >> 2;
    const int lr1 = lr0 + 64;
    const int lkv = (tid & 3) << 3;

    float acc[2][8][4];
#pragma unroll
    for (int i = 0; i < 2; i++)
#pragma unroll
        for (int j = 0; j < 8; j++)
#pragma unroll
            for (int q = 0; q < 4; q++) acc[i][j][q] = 0.f;

    gt_load_async(smb, 0, 0, Ah, Al, Bh, Bl, rowBase, colBase, M, K, lr0, lr1, lkv);
    CP_COMMIT();

    const int NKB = K / GBK;
    int buf = 0;
    for (int kb = 0; kb < NKB; kb++) {
        const bool has = (kb + 1) < NKB;
        if (has) {
            gt_load_async(smb, buf ^ 1, (kb + 1) * GBK, Ah, Al, Bh, Bl,
                          rowBase, colBase, M, K, lr0, lr1, lkv);
            CP_COMMIT();
            CP_WAIT1();
        } else {
            CP_WAIT0();
        }
        __syncthreads();

        const bf16* base = sm + buf * 4 * TSZ;
#pragma unroll
        for (int ks = 0; ks < 2; ks++) {
            const int k0 = ks * 16;
            u32 afr[2][2][4];
#pragma unroll
            for (int rt = 0; rt < 2; rt++) {
#pragma unroll
                for (int h = 0; h < 2; h++) {
                    const bf16* p = base + h * TSZ + (wRow + rt * 16 + ar) * ASTR + k0 + ac;
                    afr[rt][h][0] = *(const u32*)p;
                    afr[rt][h][1] = *(const u32*)(p + 8 * ASTR);
                    afr[rt][h][2] = *(const u32*)(p + 8);
                    afr[rt][h][3] = *(const u32*)(p + 8 * ASTR + 8);
                }
            }
            u32 bfr[8][2][2];
#pragma unroll
            for (int ct = 0; ct < 8; ct++) {
                const bf16* q = base + 2 * TSZ + (wCol + ct * 8 + ar) * ASTR + k0 + ac;
                bfr[ct][0][0] = *(const u32*)q;
                bfr[ct][0][1] = *(const u32*)(q + 8);
                bfr[ct][1][0] = *(const u32*)(q + TSZ);
                bfr[ct][1][1] = *(const u32*)(q + TSZ + 8);
            }
#pragma unroll
            for (int ct = 0; ct < 8; ct++) {
#pragma unroll
                for (int rt = 0; rt < 2; rt++)
                    MMA_BF16(acc[rt][ct], afr[rt][0], bfr[ct][0][0], bfr[ct][0][1]);
            }
#pragma unroll
            for (int ct = 0; ct < 8; ct++) {
#pragma unroll
                for (int rt = 0; rt < 2; rt++)
                    MMA_BF16(acc[rt][ct], afr[rt][0], bfr[ct][1][0], bfr[ct][1][1]);
            }
#pragma unroll
            for (int ct = 0; ct < 8; ct++) {
#pragma unroll
                for (int rt = 0; rt < 2; rt++)
                    MMA_BF16(acc[rt][ct], afr[rt][1], bfr[ct][0][0], bfr[ct][0][1]);
            }
        }
        __syncthreads();
        buf ^= 1;
    }

    const int doRelu = flags & 1;
    const int wF = flags & 2;
    const int wP = flags & 4;
#pragma unroll
    for (int rt = 0; rt < 2; rt++) {
#pragma unroll
        for (int ct = 0; ct < 8; ct++) {
            int r = rowBase + wRow + rt * 16 + ar;
            int c = colBase + wCol + ct * 8 + ac;
            float b0v = bias ? __ldg(&bias[c]) : 0.f;
            float b1v = bias ? __ldg(&bias[c + 1]) : 0.f;
            float v0 = acc[rt][ct][0] + b0v;
            float v1 = acc[rt][ct][1] + b1v;
            float v2 = acc[rt][ct][2] + b0v;
            float v3 = acc[rt][ct][3] + b1v;
            if (doRelu) {
                v0 = fmaxf(v0, 0.f); v1 = fmaxf(v1, 0.f);
                v2 = fmaxf(v2, 0.f); v3 = fmaxf(v3, 0.f);
            }
            if (r < M) {
                size_t o = (size_t)r * Nc + c;
                if (wF) *(float2*)(C + o) = make_float2(v0, v1);
                if (wP) split_store2(CH + o, CL + o, v0, v1);
            }
            if (r + 8 < M) {
                size_t o = (size_t)(r + 8) * Nc + c;
                if (wF) *(float2*)(C + o) = make_float2(v2, v3);
                if (wP) split_store2(CH + o, CL + o, v2, v3);
            }
        }
    }
}

// ---------------- fused preproc stage 1 (all independent work, block-partitioned) ----------------
// ranges: [0,782) edge_mlp | [782,861) zero cnt | [861,3997) pack_b3 | [3997,4445) pack_b1
//         | [4445,4893) pack_b2 | [4893,5789) pack_buv | [5789,5981) pack_blh | [5981,75981) gemm_k8
#define B_MLP 782
#define B_Z   79
#define B_P3  3136
#define B_P1  448
#define B_P2  448
#define B_PUV 896
#define B_PLH 192
#define B_K8  70000
#define PRE1_GRID (B_MLP + B_Z + B_P3 + B_P1 + B_P2 + B_PUV + B_PLH + B_K8)

__device__ void dev_edge_mlp(int blk, const float* ea,
    const float* w1, const float* bb1, const float* w2, const float* bb2,
    const float* w3, const float* bb3, float* outp)
{
    __shared__ float s1[NEA * 28];
    __shared__ float sb1[28];
    __shared__ float s2[28 * 28];
    __shared__ float sb2[28];
    __shared__ float s3[28];
    __shared__ float sb3v[1];
    for (int i = threadIdx.x; i < NEA * 28; i += 256) s1[i] = w1[i];
    for (int i = threadIdx.x; i < 28; i += 256) {
        sb1[i] = bb1[i];
        sb2[i] = bb2[i];
        s3[i] = w3[i];
    }
    for (int i = threadIdx.x; i < 28 * 28; i += 256) s2[i] = w2[i];
    if (threadIdx.x == 0) sb3v[0] = bb3[0];
    __syncthreads();

    int e = blk * 256 + threadIdx.x;
    if (e >= E_EDGES) return;
    float a[NEA];
#pragma unroll
    for (int k = 0; k < NEA; k++) a[k] = ea[(size_t)e * NEA + k];
    float t[28];
#pragma unroll
    for (int j = 0; j < 28; j++) {
        float v = sb1[j];
#pragma unroll
        for (int k = 0; k < NEA; k++) v += a[k] * s1[k * 28 + j];
        t[j] = fmaxf(v, 0.f);
    }
    float u[28];
#pragma unroll
    for (int j = 0; j < 28; j++) {
        float v = sb2[j];
#pragma unroll
        for (int k = 0; k < 28; k++) v += t[k] * s2[k * 28 + j];
        u[j] = fmaxf(v, 0.f);
    }
    float z = sb3v[0];
#pragma unroll
    for (int k = 0; k < 28; k++) z += u[k] * s3[k];
    outp[e] = 1.f / (1.f + expf(-z));
}

__global__ __launch_bounds__(256) void pre1_kernel(
    const float* __restrict__ ea,
    const float* __restrict__ ew1, const float* __restrict__ eb1,
    const float* __restrict__ ew2, const float* __restrict__ eb2,
    const float* __restrict__ ew3, const float* __restrict__ eb3,
    float* __restrict__ ew, int* __restrict__ cnt,
    const float* __restrict__ W1, bf16* __restrict__ B1h, bf16* __restrict__ B1l,
    const float* __restrict__ W2, bf16* __restrict__ B2h, bf16* __restrict__ B2l,
    const float* __restrict__ W3, bf16* __restrict__ B3h, bf16* __restrict__ B3l,
    const float* __restrict__ lw0, bf16* __restrict__ Buvh, bf16* __restrict__ Buvl,
    const float* __restrict__ lwh, bf16* __restrict__ Blhh, bf16* __restrict__ Blhl,
    const float* __restrict__ x, const float* __restrict__ W0, float* __restrict__ hw)
{
    int b = blockIdx.x;
    if (b < B_MLP) {
        dev_edge_mlp(b, ea, ew1, eb1, ew2, eb2, ew3, eb3, ew);
        return;
    }
    b -= B_MLP;
    if (b < B_Z) {
        int i = b * 256 + threadIdx.x;
        if (i < N_NODES) cnt[i] = 0;
        return;
    }
    b -= B_Z;
    if (b < B_P3) {
        int idx = b * 256 + threadIdx.x;
        int c = idx / HC;
        int k = idx % HC;
        int i = c >> 7;
        int j = c & 127;
        split1(W3[((size_t)i * HC + k) * HDIM + j], &B3h[idx], &B3l[idx]);
        return;
    }
    b -= B_P3;
    if (b < B_P1) {
        int idx = b * 256 + threadIdx.x;
        int n = idx / HC;
        int k = idx % HC;
        split1(W1[(size_t)k * HDIM + n], &B1h[idx], &B1l[idx]);
        return;
    }
    b -= B_P1;
    if (b < B_P2) {
        int idx = b * 256 + threadIdx.x;
        int c = idx / HDIM;
        int k = idx % HDIM;
        int i = c >> 7;
        int j = c & 127;
        split1(W2[((size_t)i * HDIM + k) * HDIM + j], &B2h[idx], &B2l[idx]);
        return;
    }
    b -= B_P2;
    if (b < B_PUV) {
        int idx = b * 256 + threadIdx.x;
        int c = idx / HC;
        int k = idx % HC;
        float v = (c < 128) ? lw0[(size_t)k * 128 + c] : lw0[(size_t)(HC + k) * 128 + (c - 128)];
        split1(v, &Buvh[idx], &Buvl[idx]);
        return;
    }
    b -= B_PUV;
    if (b < B_PLH) {
        int idx = b * 256 + threadIdx.x;
        if (idx < 3 * HLDIM * HLDIM) {
            int i = idx / (HLDIM * HLDIM);
            int n = (idx / HLDIM) % HLDIM;
            int k = idx % HLDIM;
            split1(lwh[((size_t)i * HLDIM + k) * HLDIM + n], &Blhh[idx], &Blhl[idx]);
        }
        return;
    }
    b -= B_PLH;
    {
        // gemm_k8 with W0 pack index folded in: W0r[k*HC+c] == W0[(i*DIN+k)*HDIM+j]
        int idx = b * 256 + threadIdx.x;
        if (idx >= N_NODES * HC) return;
        int m = idx / HC;
        int c = idx % HC;
        int i = c >> 7;
        int j = c & 127;
        float v = 0.f;
#pragma unroll
        for (int k = 0; k < DIN; k++)
            v += __ldg(&x[m * DIN + k]) * __ldg(&W0[((size_t)i * DIN + k) * HDIM + j]);
        hw[idx] = v;
    }
}

// ---------------- CSR build ----------------
__global__ void count_kernel(const int* __restrict__ ei, int* __restrict__ cnt, int E) {
    int e = blockIdx.x * blockDim.x + threadIdx.x;
    if (e < E) atomicAdd(&cnt[ei[E + e]], 1);
}
#define SCAN_C ((N_NODES + 1023) / 1024)
__global__ __launch_bounds__(1024) void scan_kernel(
    const int* __restrict__ cnt, int* __restrict__ rowptr, int* __restrict__ cursor)
{
    __shared__ int warpsum[32];
    const int t = threadIdx.x;
    const int lane = t & 31;
    const int wrp = t >> 5;
    const int base = t * SCAN_C;
    int vals[SCAN_C];
    int local = 0;
#pragma unroll
    for (int i = 0; i < SCAN_C; i++) {
        int idx = base + i;
        vals[i] = (idx < N_NODES) ? cnt[idx] : 0;
        local += vals[i];
    }
    int sc = local;
#pragma unroll
    for (int off = 1; off < 32; off <<= 1) {
        int v = __shfl_up_sync(0xffffffffu, sc, off);
        if (lane >= off) sc += v;
    }
    if (lane == 31) warpsum[wrp] = sc;
    __syncthreads();
    if (wrp == 0) {
        int ws = warpsum[lane];
#pragma unroll
        for (int off = 1; off < 32; off <<= 1) {
            int v = __shfl_up_sync(0xffffffffu, ws, off);
            if (lane >= off) ws += v;
        }
        warpsum[lane] = ws;
    }
    __syncthreads();
    int run = (wrp > 0 ? warpsum[wrp - 1] : 0) + (sc - local);
    if (t == 0) rowptr[0] = 0;
#pragma unroll
    for (int i = 0; i < SCAN_C; i++) {
        int idx = base + i;
        if (idx < N_NODES) {
            cursor[idx] = run;
            run += vals[i];
            rowptr[idx + 1] = run;
        }
    }
}
__global__ void csr_fill_kernel(const int* __restrict__ ei, int* __restrict__ cursor,
                                int* __restrict__ csr_r, int* __restrict__ csr_e, int E)
{
    int e = blockIdx.x * blockDim.x + threadIdx.x;
    if (e >= E) return;
    int r = ei[e];
    int c = ei[E + e];
    int pos = atomicAdd(&cursor[c], 1);
    csr_r[pos] = r;
    csr_e[pos] = e;
}

// ---------------- degrees via CSR ----------------
__global__ void deg_csr_kernel(const int* __restrict__ rowptr, const int* __restrict__ csr_e,
                               const float* __restrict__ ea, const float* __restrict__ ew,
                               float* __restrict__ dis)
{
    int idx = blockIdx.x * blockDim.x + threadIdx.x;
    if (idx >= 8 * N_NODES) return;
    int i = idx / N_NODES;
    int v = idx % N_NODES;
    int p0 = rowptr[v];
    int p1 = rowptr[v + 1];
    float s = 1.0f;
    if (i < NEA) {
        for (int p = p0; p < p1; p++) s += __ldg(&ea[(size_t)csr_e[p] * NEA + i]);
    } else {
        for (int p = p0; p < p1; p++) s += __ldg(&ew[csr_e[p]]);
    }
    dis[idx] = rsqrtf(s);
}

// ---------------- CSR scatter, channel-split: one warp per (node, channel) ----------------
__global__ __launch_bounds__(256) void scatter7_csr_kernel(
    const float* __restrict__ hw, bf16* __restrict__ outH, bf16* __restrict__ outL,
    const int* __restrict__ rowptr, const int* __restrict__ csr_r, const int* __restrict__ csr_e,
    const float* __restrict__ ea, const float* __restrict__ dis,
    const float* __restrict__ bias)
{
    int w = (blockIdx.x * blockDim.x + threadIdx.x) >> 5;
    int lane = threadIdx.x & 31;
    if (w >= N_NODES * NEA) return;
    int i = w % NEA;
    int c = w / NEA;

    float dc = __ldg(&dis[i * N_NODES + c]);
    float4 acc;
    {
        float4 v = *(const float4*)(hw + (size_t)c * HC + i * HDIM + lane * 4);
        float4 b = *(const float4*)(bias + i * HDIM + lane * 4);
        float s = dc * dc;
        acc.x = b.x + s * v.x;
        acc.y = b.y + s * v.y;
        acc.z = b.z + s * v.z;
        acc.w = b.w + s * v.w;
    }

    int p0 = __ldg(&rowptr[c]);
    int p1 = __ldg(&rowptr[c + 1]);
    if (p0 < p1) {
        int r = __ldg(&csr_r[p0]);
        int e = __ldg(&csr_e[p0]);
        for (int p = p0; p < p1; p++) {
            int rn = 0, en = 0;
            if (p + 1 < p1) {
                rn = __ldg(&csr_r[p + 1]);
                en = __ldg(&csr_e[p + 1]);
            }
            float co = __ldg(&dis[i * N_NODES + r]) * dc * __ldg(&ea[(size_t)e * NEA + i]);
            float4 v = *(const float4*)(hw + (size_t)r * HC + i * HDIM + lane * 4);
            acc.x += co * v.x;
            acc.y += co * v.y;
            acc.z += co * v.z;
            acc.w += co * v.w;
            r = rn;
            e = en;
        }
    }

    acc.x = fmaxf(acc.x, 0.f);
    acc.y = fmaxf(acc.y, 0.f);
    acc.z = fmaxf(acc.z, 0.f);
    acc.w = fmaxf(acc.w, 0.f);
    size_t o = (size_t)c * HC + i * HDIM + lane * 4;
    split_store4(outH + o, outL + o, acc);
}

// ---------------- CSR scatter, single channel -> bf16 pair ----------------
__global__ __launch_bounds__(256) void scatter1_csr_kernel(
    const float* __restrict__ hw, bf16* __restrict__ outH, bf16* __restrict__ outL,
    const int* __restrict__ rowptr, const int* __restrict__ csr_r, const int* __restrict__ csr_e,
    const float* __restrict__ ewv, const float* __restrict__ dis7,
    const float* __restrict__ bias)
{
    int c = (blockIdx.x * blockDim.x + threadIdx.x) >> 5;
    int lane = threadIdx.x & 31;
    if (c >= N_NODES) return;

    float dc = __ldg(&dis7[c]);
    float4 acc;
    {
        float4 v = *(const float4*)(hw + (size_t)c * HDIM + lane * 4);
        float4 b = *(const float4*)(bias + lane * 4);
        float s = dc * dc;
        acc.x = b.x + s * v.x;
        acc.y = b.y + s * v.y;
        acc.z = b.z + s * v.z;
        acc.w = b.w + s * v.w;
    }
    int p0 = __ldg(&rowptr[c]);
    int p1 = __ldg(&rowptr[c + 1]);
    if (p0 < p1) {
        int r = __ldg(&csr_r[p0]);
        int e = __ldg(&csr_e[p0]);
        for (int p = p0; p < p1; p++) {
            int rn = 0, en = 0;
            if (p + 1 < p1) {
                rn = __ldg(&csr_r[p + 1]);
                en = __ldg(&csr_e[p + 1]);
            }
            float co = __ldg(&dis7[r]) * dc * __ldg(&ewv[e]);
            float4 v = *(const float4*)(hw + (size_t)r * HDIM + lane * 4);
            acc.x += co * v.x;
            acc.y += co * v.y;
            acc.z += co * v.z;
            acc.w += co * v.w;
            r = rn;
            e = en;
        }
    }
    acc.x = fmaxf(acc.x, 0.f);
    acc.y = fmaxf(acc.y, 0.f);
    acc.z = fmaxf(acc.z, 0.f);
    acc.w = fmaxf(acc.w, 0.f);
    size_t o = (size_t)c * HDIM + lane * 4;
    split_store4(outH + o, outL + o, acc);
}

// ---------------- link head ----------------
__global__ void build_h0_kernel(const float* __restrict__ UV,
                                const float* __restrict__ lb0, const int* __restrict__ eit,
                                bf16* __restrict__ Hh, bf16* __restrict__ Hl)
{
    size_t idx = (size_t)blockIdx.x * blockDim.x + threadIdx.x;
    if (idx >= (size_t)2 * ET_EDGES * HLDIM) return;
    int e = (int)(idx >> 7);
    int j = (int)(idx & 127);
    int a;
    int b;
    if (e < ET_EDGES) {
        a = eit[e];
        b = eit[ET_EDGES + e];
    } else {
        int e2 = e - ET_EDGES;
        a = eit[ET_EDGES + e2];
        b = eit[e2];
    }
    float v = UV[(size_t)a * 256 + j] + UV[(size_t)b * 256 + 128 + j] + lb0[j];
    v = fmaxf(v, 0.f);
    split1(v, &Hh[idx], &Hl[idx]);
}

__global__ __launch_bounds__(256) void gemm_out_kernel(
    const float* __restrict__ Hm, const float* __restrict__ lw4,
    const float* __restrict__ lb4, float* __restrict__ T, int M)
{
    int w = (blockIdx.x * blockDim.x + threadIdx.x) >> 5;
    int lane = threadIdx.x & 31;
    if (w >= M) return;
    float h0 = Hm[(size_t)w * HLDIM + lane];
    float h1 = Hm[(size_t)w * HLDIM + 32 + lane];
    float h2 = Hm[(size_t)w * HLDIM + 64 + lane];
    float h3 = Hm[(size_t)w * HLDIM + 96 + lane];
    float acc[4];
#pragma unroll
    for (int c = 0; c < 4; c++) {
        acc[c] = h0 * __ldg(&lw4[lane * 4 + c])
               + h1 * __ldg(&lw4[(lane + 32) * 4 + c])
               + h2 * __ldg(&lw4[(lane + 64) * 4 + c])
               + h3 * __ldg(&lw4[(lane + 96) * 4 + c]);
    }
#pragma unroll
    for (int off = 16; off > 0; off >>= 1) {
#pragma unroll
        for (int c = 0; c < 4; c++) acc[c] += __shfl_down_sync(0xffffffffu, acc[c], off);
    }
    if (lane == 0) {
#pragma unroll
        for (int c = 0; c < 4; c++) T[(size_t)w * 4 + c] = acc[c] + lb4[c];
    }
}

__global__ void combine_kernel(const float* __restrict__ T, float* __restrict__ out) {
    int idx = blockIdx.x * blockDim.x + threadIdx.x;
    if (idx >= ET_EDGES * 4) return;
    int e = idx >> 2;
    int c = idx & 3;
    int pc = (c == 1) ? 2 : ((c == 2) ? 1 : c);
    out[idx] = 0.5f * (T[(size_t)e * 4 + c] + T[(size_t)(ET_EDGES + e) * 4 + pc]);
}

// ---------------- host orchestration ----------------
static inline int cdiv(size_t a, int b) { return (int)((a + b - 1) / b); }

extern "C" void kernel_launch(void* const* d_in, const int* in_sizes, int n_in,
                              void* d_out, int out_size)
{
    const float* x    = (const float*)d_in[0];
    const int*   ei   = (const int*)  d_in[1];
    const float* ea   = (const float*)d_in[2];
    const int*   eit  = (const int*)  d_in[3];
    const float* W0   = (const float*)d_in[4];
    const float* b0   = (const float*)d_in[5];
    const float* W1   = (const float*)d_in[6];
    const float* b1   = (const float*)d_in[7];
    const float* W2   = (const float*)d_in[8];
    const float* b2   = (const float*)d_in[9];
    const float* W3   = (const float*)d_in[10];
    const float* b3   = (const float*)d_in[11];
    const float* ew1  = (const float*)d_in[12];
    const float* eb1  = (const float*)d_in[13];
    const float* ew2  = (const float*)d_in[14];
    const float* eb2  = (const float*)d_in[15];
    const float* ew3  = (const float*)d_in[16];
    const float* eb3  = (const float*)d_in[17];
    const float* lw0  = (const float*)d_in[18];
    const float* lb0  = (const float*)d_in[19];
    const float* lwh  = (const float*)d_in[20];
    const float* lbh  = (const float*)d_in[21];
    const float* lw4  = (const float*)d_in[22];
    const float* lb4  = (const float*)d_in[23];
    float* out = (float*)d_out;

    float *ew, *dis, *hw, *hw128, *UV, *Hbf, *T;
    bf16 *x1h, *x1l, *x2h, *x2l, *x3h, *x3l, *x4h, *x4l;
    bf16 *Hah, *Hal, *Hbh, *Hbl;
    bf16 *B1h, *B1l, *B2h, *B2l, *B3h, *B3l, *Buvh, *Buvl, *Blhh, *Blhl;
    int *cnt, *cursor, *rowptr, *csr_r, *csr_e;
    cudaGetSymbolAddress((void**)&ew,    g_ew);
    cudaGetSymbolAddress((void**)&dis,   g_dis);
    cudaGetSymbolAddress((void**)&hw,    g_hw);
    cudaGetSymbolAddress((void**)&hw128, g_hw128);
    cudaGetSymbolAddress((void**)&UV,    g_UV);
    cudaGetSymbolAddress((void**)&Hbf,   g_Hb_f32);
    cudaGetSymbolAddress((void**)&T,     g_T);
    cudaGetSymbolAddress((void**)&x1h,   g_x1h);
    cudaGetSymbolAddress((void**)&x1l,   g_x1l);
    cudaGetSymbolAddress((void**)&x2h,   g_x2h);
    cudaGetSymbolAddress((void**)&x2l,   g_x2l);
    cudaGetSymbolAddress((void**)&x3h,   g_x3h);
    cudaGetSymbolAddress((void**)&x3l,   g_x3l);
    cudaGetSymbolAddress((void**)&x4h,   g_x4h);
    cudaGetSymbolAddress((void**)&x4l,   g_x4l);
    cudaGetSymbolAddress((void**)&Hah,   g_Hah);
    cudaGetSymbolAddress((void**)&Hal,   g_Hal);
    cudaGetSymbolAddress((void**)&Hbh,   g_Hbh);
    cudaGetSymbolAddress((void**)&Hbl,   g_Hbl);
    cudaGetSymbolAddress((void**)&B1h,   g_B1h);
    cudaGetSymbolAddress((void**)&B1l,   g_B1l);
    cudaGetSymbolAddress((void**)&B2h,   g_B2h);
    cudaGetSymbolAddress((void**)&B2l,   g_B2l);
    cudaGetSymbolAddress((void**)&B3h,   g_B3h);
    cudaGetSymbolAddress((void**)&B3l,   g_B3l);
    cudaGetSymbolAddress((void**)&Buvh,  g_Buvh);
    cudaGetSymbolAddress((void**)&Buvl,  g_Buvl);
    cudaGetSymbolAddress((void**)&Blhh,  g_Blhh);
    cudaGetSymbolAddress((void**)&Blhl,  g_Blhl);
    cudaGetSymbolAddress((void**)&cnt,   g_cnt);
    cudaGetSymbolAddress((void**)&cursor,g_cursor);
    cudaGetSymbolAddress((void**)&rowptr,g_rowptr);
    cudaGetSymbolAddress((void**)&csr_r, g_csr_r);
    cudaGetSymbolAddress((void**)&csr_e, g_csr_e);

    cudaFuncSetAttribute(gemm_mma_kernel, cudaFuncAttributeMaxDynamicSharedMemorySize, MMA_SMEM);

    const int TB = 256;
    const int M2 = 2 * ET_EDGES;
    const int SCAT7_GRID = cdiv((size_t)N_NODES * NEA * 32, TB);
    const int SCAT1_GRID = cdiv((size_t)N_NODES * 32, TB);
    const int GRY = cdiv(N_NODES, 128);
    const int GRY2 = cdiv(M2, 128);

    // fused preproc: edge-MLP | zero | all packs | layer-1 GEMM (independent, one kernel)
    pre1_kernel<<<PRE1_GRID, TB>>>(
        ea, ew1, eb1, ew2, eb2, ew3, eb3, ew, cnt,
        W1, B1h, B1l, W2, B2h, B2l, W3, B3h, B3l,
        lw0, Buvh, Buvl, lwh, Blhh, Blhl,
        x, W0, hw);

    count_kernel<<<cdiv(E_EDGES, TB), TB>>>(ei, cnt, E_EDGES);
    scan_kernel<<<1, 1024>>>(cnt, rowptr, cursor);
    csr_fill_kernel<<<cdiv(E_EDGES, TB), TB>>>(ei, cursor, csr_r, csr_e, E_EDGES);
    deg_csr_kernel<<<cdiv(8 * N_NODES, TB), TB>>>(rowptr, csr_e, ea, ew, dis);

    // layer 1 scatter
    scatter7_csr_kernel<<<SCAT7_GRID, TB>>>(hw, x1h, x1l, rowptr, csr_r, csr_e, ea, dis, b0);

    // layer 2
    gemm_mma_kernel<<<dim3(1, GRY), 256, MMA_SMEM>>>(
        x1h, x1l, B1h, B1l, hw128, (bf16*)0, (bf16*)0, N_NODES, HC, HDIM, (const float*)0, 2);
    scatter1_csr_kernel<<<SCAT1_GRID, TB>>>(hw128, x2h, x2l, rowptr, csr_r, csr_e, ew,
                                            dis + NEA * N_NODES, b1);

    // layer 3
    gemm_mma_kernel<<<dim3(7, GRY), 256, MMA_SMEM>>>(
        x2h, x2l, B2h, B2l, hw, (bf16*)0, (bf16*)0, N_NODES, HDIM, HC, (const float*)0, 2);
    scatter7_csr_kernel<<<SCAT7_GRID, TB>>>(hw, x3h, x3l, rowptr, csr_r, csr_e, ea, dis, b2);

    // layer 4
    gemm_mma_kernel<<<dim3(7, GRY), 256, MMA_SMEM>>>(
        x3h, x3l, B3h, B3l, hw, (bf16*)0, (bf16*)0, N_NODES, HC, HC, (const float*)0, 2);
    scatter7_csr_kernel<<<SCAT7_GRID, TB>>>(hw, x4h, x4l, rowptr, csr_r, csr_e, ea, dis, b3);

    // link head: UV = x4 @ Wuv
    gemm_mma_kernel<<<dim3(2, GRY), 256, MMA_SMEM>>>(
        x4h, x4l, Buvh, Buvl, UV, (bf16*)0, (bf16*)0, N_NODES, HC, 256, (const float*)0, 2);

    build_h0_kernel<<<cdiv((size_t)M2 * HLDIM, TB), TB>>>(UV, lb0, eit, Hah, Hal);

    gemm_mma_kernel<<<dim3(1, GRY2), 256, MMA_SMEM>>>(
        Hah, Hal, Blhh, Blhl, (float*)0, Hbh, Hbl, M2, HLDIM, HLDIM, lbh, 1 | 4);
    gemm_mma_kernel<<<dim3(1, GRY2), 256, MMA_SMEM>>>(
        Hbh, Hbl, Blhh + HLDIM * HLDIM, Blhl + HLDIM * HLDIM, (float*)0, Hah, Hal,
        M2, HLDIM, HLDIM, lbh + HLDIM, 1 | 4);
    gemm_mma_kernel<<<dim3(1, GRY2), 256, MMA_SMEM>>>(
        Hah, Hal, Blhh + 2 * HLDIM * HLDIM, Blhl + 2 * HLDIM * HLDIM, Hbf, (bf16*)0, (bf16*)0,
        M2, HLDIM, HLDIM, lbh + 2 * HLDIM, 1 | 2);

    gemm_out_kernel<<<cdiv((size_t)M2 * 32, TB), TB>>>(Hbf, lw4, lb4, T, M2);
    combine_kernel<<<cdiv(ET_EDGES * 4, TB), TB>>>(T, out);
}

// round 17
// speedup vs baseline: 1.0979x; 1.0979x over previous
#include <cuda_runtime.h>
#include <cuda_bf16.h>
#include <stdint.h>
#include <math.h>

#define N_NODES 20000
#define E_EDGES 200000
#define ET_EDGES 40000
#define DIN 8
#define HDIM 128
#define NEA 7
#define HC 896
#define HLDIM 128
#define OUTD 4

typedef unsigned long long u64;
typedef unsigned int u32;
typedef __nv_bfloat16 bf16;

// ---------------- scratch ----------------
static __device__ float g_ew[E_EDGES];
static __device__ float g_dis[8 * N_NODES];
static __device__ float g_hw[(size_t)N_NODES * HC];
static __device__ float g_hw128[(size_t)N_NODES * HDIM];
static __device__ float g_UV[(size_t)N_NODES * 256];
static __device__ float g_Hb_f32[(size_t)2 * ET_EDGES * HLDIM];
static __device__ bf16 g_x1h[(size_t)N_NODES * HC];
static __device__ bf16 g_x1l[(size_t)N_NODES * HC];
static __device__ bf16 g_x2h[(size_t)N_NODES * HDIM];
static __device__ bf16 g_x2l[(size_t)N_NODES * HDIM];
static __device__ bf16 g_x3h[(size_t)N_NODES * HC];
static __device__ bf16 g_x3l[(size_t)N_NODES * HC];
static __device__ bf16 g_x4h[(size_t)N_NODES * HC];
static __device__ bf16 g_x4l[(size_t)N_NODES * HC];
static __device__ bf16 g_Hah[(size_t)2 * ET_EDGES * HLDIM];
static __device__ bf16 g_Hal[(size_t)2 * ET_EDGES * HLDIM];
static __device__ bf16 g_Hbh[(size_t)2 * ET_EDGES * HLDIM];
static __device__ bf16 g_Hbl[(size_t)2 * ET_EDGES * HLDIM];
static __device__ bf16 g_B1h[HDIM * HC];
static __device__ bf16 g_B1l[HDIM * HC];
static __device__ bf16 g_B2h[HC * HDIM];
static __device__ bf16 g_B2l[HC * HDIM];
static __device__ bf16 g_B3h[(size_t)HC * HC];
static __device__ bf16 g_B3l[(size_t)HC * HC];
static __device__ bf16 g_Buvh[256 * HC];
static __device__ bf16 g_Buvl[256 * HC];
static __device__ bf16 g_Blhh[3 * HLDIM * HLDIM];
static __device__ bf16 g_Blhl[3 * HLDIM * HLDIM];
static __device__ int g_cnt[N_NODES];
static __device__ int g_cursor[N_NODES];
static __device__ int g_rowptr[N_NODES + 1];
static __device__ int g_csr_r[E_EDGES];
static __device__ int g_csr_e[E_EDGES];

// ---------------- bf16 split helpers ----------------
__device__ __forceinline__ void split1(float v, bf16* ph, bf16* pl) {
    bf16 h = __float2bfloat16(v);
    *ph = h;
    *pl = __float2bfloat16(v - __bfloat162float(h));
}
__device__ __forceinline__ void split_store4(bf16* ph, bf16* pl, float4 v) {
    bf16 h0 = __float2bfloat16(v.x);
    bf16 h1 = __float2bfloat16(v.y);
    bf16 h2 = __float2bfloat16(v.z);
    bf16 h3 = __float2bfloat16(v.w);
    bf16 l0 = __float2bfloat16(v.x - __bfloat162float(h0));
    bf16 l1 = __float2bfloat16(v.y - __bfloat162float(h1));
    bf16 l2 = __float2bfloat16(v.z - __bfloat162float(h2));
    bf16 l3 = __float2bfloat16(v.w - __bfloat162float(h3));
    __nv_bfloat162* H = reinterpret_cast<__nv_bfloat162*>(ph);
    __nv_bfloat162* L = reinterpret_cast<__nv_bfloat162*>(pl);
    H[0] = __halves2bfloat162(h0, h1);
    H[1] = __halves2bfloat162(h2, h3);
    L[0] = __halves2bfloat162(l0, l1);
    L[1] = __halves2bfloat162(l2, l3);
}
__device__ __forceinline__ void split_store2(bf16* ph, bf16* pl, float x, float y) {
    bf16 hx = __float2bfloat16(x);
    bf16 hy = __float2bfloat16(y);
    bf16 lx = __float2bfloat16(x - __bfloat162float(hx));
    bf16 ly = __float2bfloat16(y - __bfloat162float(hy));
    *reinterpret_cast<__nv_bfloat162*>(ph) = __halves2bfloat162(hx, hy);
    *reinterpret_cast<__nv_bfloat162*>(pl) = __halves2bfloat162(lx, ly);
}

__device__ __forceinline__ u32 smem_u32(const void* p) {
    u32 a;
    asm("{ .reg .u64 t; cvta.to.shared.u64 t, %1; cvt.u32.u64 %0, t; }" : "=r"(a) : "l"(p));
    return a;
}

// ---------------- bf16 mma.sync GEMM with cp.async pipeline ----------------
#define GBK 32
#define ASTR 40
#define TSZ (128 * ASTR)
#define MMA_SMEM (2 * 4 * TSZ * 2)

#define MMA_BF16(d, a, b0v, b1v) \
    asm volatile("mma.sync.aligned.m16n8k16.row.col.f32.bf16.bf16.f32 " \
        "{%0,%1,%2,%3}, {%4,%5,%6,%7}, {%8,%9}, {%0,%1,%2,%3};" \
        : "+f"((d)[0]), "+f"((d)[1]), "+f"((d)[2]), "+f"((d)[3]) \
        : "r"((a)[0]), "r"((a)[1]), "r"((a)[2]), "r"((a)[3]), "r"(b0v), "r"(b1v))

#define CP_ASYNC16(dst_u32, src_ptr, nbytes) \
    asm volatile("cp.async.cg.shared.global [%0], [%1], 16, %2;" \
                 :: "r"(dst_u32), "l"(src_ptr), "r"(nbytes) : "memory")
#define CP_COMMIT() asm volatile("cp.async.commit_group;" ::: "memory")
#define CP_WAIT1()  asm volatile("cp.async.wait_group 1;" ::: "memory")
#define CP_WAIT0()  asm volatile("cp.async.wait_group 0;" ::: "memory")

__device__ __forceinline__ void gt_load_async(
    u32 smbase, int buf, int kb,
    const bf16* Ah, const bf16* Al, const bf16* Bh, const bf16* Bl,
    int rowBase, int colBase, int M, int K, int r0, int r1, int kv)
{
    u32 base = smbase + (u32)buf * 4 * TSZ * 2;
    u32 d00 = base + (u32)(0 * TSZ + r0 * ASTR + kv) * 2;
    u32 d01 = base + (u32)(0 * TSZ + r1 * ASTR + kv) * 2;
    u32 d10 = base + (u32)(1 * TSZ + r0 * ASTR + kv) * 2;
    u32 d11 = base + (u32)(1 * TSZ + r1 * ASTR + kv) * 2;
    u32 d20 = base + (u32)(2 * TSZ + r0 * ASTR + kv) * 2;
    u32 d21 = base + (u32)(2 * TSZ + r1 * ASTR + kv) * 2;
    u32 d30 = base + (u32)(3 * TSZ + r0 * ASTR + kv) * 2;
    u32 d31 = base + (u32)(3 * TSZ + r1 * ASTR + kv) * 2;
    size_t a0 = (size_t)(rowBase + r0) * K + kb + kv;
    size_t a1 = (size_t)(rowBase + r1) * K + kb + kv;
    int n0 = ((rowBase + r0) < M) ? 16 : 0;
    int n1 = ((rowBase + r1) < M) ? 16 : 0;
    CP_ASYNC16(d00, Ah + a0, n0);
    CP_ASYNC16(d01, Ah + a1, n1);
    CP_ASYNC16(d10, Al + a0, n0);
    CP_ASYNC16(d11, Al + a1, n1);
    size_t b0 = (size_t)(colBase + r0) * K + kb + kv;
    size_t b1 = (size_t)(colBase + r1) * K + kb + kv;
    CP_ASYNC16(d20, Bh + b0, 16);
    CP_ASYNC16(d21, Bh + b1, 16);
    CP_ASYNC16(d30, Bl + b0, 16);
    CP_ASYNC16(d31, Bl + b1, 16);
}

__global__ __launch_bounds__(256)
void gemm_mma_kernel(
    const bf16* __restrict__ Ah, const bf16* __restrict__ Al,
    const bf16* __restrict__ Bh, const bf16* __restrict__ Bl,
    float* __restrict__ C, bf16* __restrict__ CH, bf16* __restrict__ CL,
    int M, int K, int Nc, const float* __restrict__ bias, int flags)
{
    extern __shared__ bf16 sm[];
    const u32 smb = smem_u32(sm);
    const int tid = threadIdx.x;
    const int wid = tid >> 5;
    const int lane = tid & 31;
    const int rowBase = blockIdx.y * 128;
    const int colBase = blockIdx.x * 128;
    const int wRow = (wid & 3) * 32;
    const int wCol = (wid >> 2) * 64;
    const int ar = lane >> 2;
    const int ac = (lane & 3) << 1;

    const int lr0 = tid >> 2;
    const int lr1 = lr0 + 64;
    const int lkv = (tid & 3) << 3;

    float acc[2][8][4];
#pragma unroll
    for (int i = 0; i < 2; i++)
#pragma unroll
        for (int j = 0; j < 8; j++)
#pragma unroll
            for (int q = 0; q < 4; q++) acc[i][j][q] = 0.f;

    gt_load_async(smb, 0, 0, Ah, Al, Bh, Bl, rowBase, colBase, M, K, lr0, lr1, lkv);
    CP_COMMIT();

    const int NKB = K / GBK;
    int buf = 0;
    for (int kb = 0; kb < NKB; kb++) {
        const bool has = (kb + 1) < NKB;
        if (has) {
            gt_load_async(smb, buf ^ 1, (kb + 1) * GBK, Ah, Al, Bh, Bl,
                          rowBase, colBase, M, K, lr0, lr1, lkv);
            CP_COMMIT();
            CP_WAIT1();
        } else {
            CP_WAIT0();
        }
        __syncthreads();

        const bf16* base = sm + buf * 4 * TSZ;
#pragma unroll
        for (int ks = 0; ks < 2; ks++) {
            const int k0 = ks * 16;
            u32 afr[2][2][4];
#pragma unroll
            for (int rt = 0; rt < 2; rt++) {
#pragma unroll
                for (int h = 0; h < 2; h++) {
                    const bf16* p = base + h * TSZ + (wRow + rt * 16 + ar) * ASTR + k0 + ac;
                    afr[rt][h][0] = *(const u32*)p;
                    afr[rt][h][1] = *(const u32*)(p + 8 * ASTR);
                    afr[rt][h][2] = *(const u32*)(p + 8);
                    afr[rt][h][3] = *(const u32*)(p + 8 * ASTR + 8);
                }
            }
            u32 bfr[8][2][2];
#pragma unroll
            for (int ct = 0; ct < 8; ct++) {
                const bf16* q = base + 2 * TSZ + (wCol + ct * 8 + ar) * ASTR + k0 + ac;
                bfr[ct][0][0] = *(const u32*)q;
                bfr[ct][0][1] = *(const u32*)(q + 8);
                bfr[ct][1][0] = *(const u32*)(q + TSZ);
                bfr[ct][1][1] = *(const u32*)(q + TSZ + 8);
            }
#pragma unroll
            for (int ct = 0; ct < 8; ct++) {
#pragma unroll
                for (int rt = 0; rt < 2; rt++)
                    MMA_BF16(acc[rt][ct], afr[rt][0], bfr[ct][0][0], bfr[ct][0][1]);
            }
#pragma unroll
            for (int ct = 0; ct < 8; ct++) {
#pragma unroll
                for (int rt = 0; rt < 2; rt++)
                    MMA_BF16(acc[rt][ct], afr[rt][0], bfr[ct][1][0], bfr[ct][1][1]);
            }
#pragma unroll
            for (int ct = 0; ct < 8; ct++) {
#pragma unroll
                for (int rt = 0; rt < 2; rt++)
                    MMA_BF16(acc[rt][ct], afr[rt][1], bfr[ct][0][0], bfr[ct][0][1]);
            }
        }
        __syncthreads();
        buf ^= 1;
    }

    const int doRelu = flags & 1;
    const int wF = flags & 2;
    const int wP = flags & 4;
#pragma unroll
    for (int rt = 0; rt < 2; rt++) {
#pragma unroll
        for (int ct = 0; ct < 8; ct++) {
            int r = rowBase + wRow + rt * 16 + ar;
            int c = colBase + wCol + ct * 8 + ac;
            float b0v = bias ? __ldg(&bias[c]) : 0.f;
            float b1v = bias ? __ldg(&bias[c + 1]) : 0.f;
            float v0 = acc[rt][ct][0] + b0v;
            float v1 = acc[rt][ct][1] + b1v;
            float v2 = acc[rt][ct][2] + b0v;
            float v3 = acc[rt][ct][3] + b1v;
            if (doRelu) {
                v0 = fmaxf(v0, 0.f); v1 = fmaxf(v1, 0.f);
                v2 = fmaxf(v2, 0.f); v3 = fmaxf(v3, 0.f);
            }
            if (r < M) {
                size_t o = (size_t)r * Nc + c;
                if (wF) *(float2*)(C + o) = make_float2(v0, v1);
                if (wP) split_store2(CH + o, CL + o, v0, v1);
            }
            if (r + 8 < M) {
                size_t o = (size_t)(r + 8) * Nc + c;
                if (wF) *(float2*)(C + o) = make_float2(v2, v3);
                if (wP) split_store2(CH + o, CL + o, v2, v3);
            }
        }
    }
}

// ---------------- edge-weight MLP ----------------
__global__ __launch_bounds__(256) void edge_mlp_kernel(
    const float* __restrict__ ea,
    const float* __restrict__ w1, const float* __restrict__ bb1,
    const float* __restrict__ w2, const float* __restrict__ bb2,
    const float* __restrict__ w3, const float* __restrict__ bb3,
    float* __restrict__ out, int E)
{
    __shared__ float s1[NEA * 28];
    __shared__ float sb1[28];
    __shared__ float s2[28 * 28];
    __shared__ float sb2[28];
    __shared__ float s3[28];
    __shared__ float sb3v[1];
    for (int i = threadIdx.x; i < NEA * 28; i += blockDim.x) s1[i] = w1[i];
    for (int i = threadIdx.x; i < 28; i += blockDim.x) {
        sb1[i] = bb1[i];
        sb2[i] = bb2[i];
        s3[i] = w3[i];
    }
    for (int i = threadIdx.x; i < 28 * 28; i += blockDim.x) s2[i] = w2[i];
    if (threadIdx.x == 0) sb3v[0] = bb3[0];
    __syncthreads();

    int e = blockIdx.x * blockDim.x + threadIdx.x;
    if (e >= E) return;
    float a[NEA];
#pragma unroll
    for (int k = 0; k < NEA; k++) a[k] = ea[(size_t)e * NEA + k];
    float t[28];
#pragma unroll
    for (int j = 0; j < 28; j++) {
        float v = sb1[j];
#pragma unroll
        for (int k = 0; k < NEA; k++) v += a[k] * s1[k * 28 + j];
        t[j] = fmaxf(v, 0.f);
    }
    float u[28];
#pragma unroll
    for (int j = 0; j < 28; j++) {
        float v = sb2[j];
#pragma unroll
        for (int k = 0; k < 28; k++) v += t[k] * s2[k * 28 + j];
        u[j] = fmaxf(v, 0.f);
    }
    float z = sb3v[0];
#pragma unroll
    for (int k = 0; k < 28; k++) z += u[k] * s3[k];
    out[e] = 1.f / (1.f + expf(-z));
}

// ---------------- CSR build ----------------
__global__ void zero_int_kernel(int* __restrict__ p, int n) {
    int i = blockIdx.x * blockDim.x + threadIdx.x;
    if (i < n) p[i] = 0;
}
__global__ void count_kernel(const int* __restrict__ ei, int* __restrict__ cnt, int E) {
    int e = blockIdx.x * blockDim.x + threadIdx.x;
    if (e < E) atomicAdd(&cnt[ei[E + e]], 1);
}
#define SCAN_C ((N_NODES + 1023) / 1024)
__global__ __launch_bounds__(1024) void scan_kernel(
    const int* __restrict__ cnt, int* __restrict__ rowptr, int* __restrict__ cursor)
{
    __shared__ int warpsum[32];
    const int t = threadIdx.x;
    const int lane = t & 31;
    const int wrp = t >> 5;
    const int base = t * SCAN_C;
    int vals[SCAN_C];
    int local = 0;
#pragma unroll
    for (int i = 0; i < SCAN_C; i++) {
        int idx = base + i;
        vals[i] = (idx < N_NODES) ? cnt[idx] : 0;
        local += vals[i];
    }
    int sc = local;
#pragma unroll
    for (int off = 1; off < 32; off <<= 1) {
        int v = __shfl_up_sync(0xffffffffu, sc, off);
        if (lane >= off) sc += v;
    }
    if (lane == 31) warpsum[wrp] = sc;
    __syncthreads();
    if (wrp == 0) {
        int ws = warpsum[lane];
#pragma unroll
        for (int off = 1; off < 32; off <<= 1) {
            int v = __shfl_up_sync(0xffffffffu, ws, off);
            if (lane >= off) ws += v;
        }
        warpsum[lane] = ws;
    }
    __syncthreads();
    int run = (wrp > 0 ? warpsum[wrp - 1] : 0) + (sc - local);
    if (t == 0) rowptr[0] = 0;
#pragma unroll
    for (int i = 0; i < SCAN_C; i++) {
        int idx = base + i;
        if (idx < N_NODES) {
            cursor[idx] = run;
            run += vals[i];
            rowptr[idx + 1] = run;
        }
    }
}
__global__ void csr_fill_kernel(const int* __restrict__ ei, int* __restrict__ cursor,
                                int* __restrict__ csr_r, int* __restrict__ csr_e, int E)
{
    int e = blockIdx.x * blockDim.x + threadIdx.x;
    if (e >= E) return;
    int r = ei[e];
    int c = ei[E + e];
    int pos = atomicAdd(&cursor[c], 1);
    csr_r[pos] = r;
    csr_e[pos] = e;
}

// ---------------- degrees: one warp per node, lanes 0-7 cover channels ----------------
__global__ __launch_bounds__(256) void deg_warp_kernel(
    const int* __restrict__ rowptr, const int* __restrict__ csr_e,
    const float* __restrict__ ea, const float* __restrict__ ew,
    float* __restrict__ dis)
{
    int w = (blockIdx.x * blockDim.x + threadIdx.x) >> 5;
    int lane = threadIdx.x & 31;
    if (w >= N_NODES) return;
    int p0 = __ldg(&rowptr[w]);
    int p1 = __ldg(&rowptr[w + 1]);
    float s = 1.0f;   // self-loop
    for (int p = p0; p < p1; p++) {
        int e = __ldg(&csr_e[p]);
        float v = 0.f;
        if (lane < NEA) v = __ldg(&ea[(size_t)e * NEA + lane]);
        else if (lane == NEA) v = __ldg(&ew[e]);
        s += v;
    }
    if (lane < 8) dis[lane * N_NODES + w] = rsqrtf(s);
}

// ---------------- weight packs ----------------
__global__ void pack_b1_kernel(const float* __restrict__ W1, bf16* __restrict__ Bh, bf16* __restrict__ Bl) {
    int idx = blockIdx.x * blockDim.x + threadIdx.x;
    if (idx >= HDIM * HC) return;
    int n = idx / HC;
    int k = idx % HC;
    split1(W1[(size_t)k * HDIM + n], &Bh[idx], &Bl[idx]);
}
__global__ void pack_b2_kernel(const float* __restrict__ W2, bf16* __restrict__ Bh, bf16* __restrict__ Bl) {
    int idx = blockIdx.x * blockDim.x + threadIdx.x;
    if (idx >= HC * HDIM) return;
    int c = idx / HDIM;
    int k = idx % HDIM;
    int i = c >> 7;
    int j = c & 127;
    split1(W2[((size_t)i * HDIM + k) * HDIM + j], &Bh[idx], &Bl[idx]);
}
__global__ void pack_b3_kernel(const float* __restrict__ W3, bf16* __restrict__ Bh, bf16* __restrict__ Bl) {
    int idx = blockIdx.x * blockDim.x + threadIdx.x;
    if (idx >= HC * HC) return;
    int c = idx / HC;
    int k = idx % HC;
    int i = c >> 7;
    int j = c & 127;
    split1(W3[((size_t)i * HC + k) * HDIM + j], &Bh[idx], &Bl[idx]);
}
__global__ void pack_buv_kernel(const float* __restrict__ lw0, bf16* __restrict__ Bh, bf16* __restrict__ Bl) {
    int idx = blockIdx.x * blockDim.x + threadIdx.x;
    if (idx >= 256 * HC) return;
    int c = idx / HC;
    int k = idx % HC;
    float v = (c < 128) ? lw0[(size_t)k * 128 + c] : lw0[(size_t)(HC + k) * 128 + (c - 128)];
    split1(v, &Bh[idx], &Bl[idx]);
}
__global__ void pack_blh_kernel(const float* __restrict__ lwh, bf16* __restrict__ Bh, bf16* __restrict__ Bl) {
    int idx = blockIdx.x * blockDim.x + threadIdx.x;
    if (idx >= 3 * HLDIM * HLDIM) return;
    int i = idx / (HLDIM * HLDIM);
    int n = (idx / HLDIM) % HLDIM;
    int k = idx % HLDIM;
    split1(lwh[((size_t)i * HLDIM + k) * HLDIM + n], &Bh[idx], &Bl[idx]);
}

// ---------------- G0: x[N,8] @ W0 (pack folded into load index) ----------------
__global__ void gemm_k8_kernel(const float* __restrict__ x, const float* __restrict__ W0,
                               float* __restrict__ out)
{
    int idx = blockIdx.x * blockDim.x + threadIdx.x;
    if (idx >= N_NODES * HC) return;
    int m = idx / HC;
    int c = idx % HC;
    int i = c >> 7;
    int j = c & 127;
    float v = 0.f;
#pragma unroll
    for (int k = 0; k < DIN; k++)
        v += __ldg(&x[m * DIN + k]) * __ldg(&W0[((size_t)i * DIN + k) * HDIM + j]);
    out[idx] = v;
}

// ---------------- CSR scatter, channel-split: one warp per (node, channel) ----------------
__global__ __launch_bounds__(256) void scatter7_csr_kernel(
    const float* __restrict__ hw, bf16* __restrict__ outH, bf16* __restrict__ outL,
    const int* __restrict__ rowptr, const int* __restrict__ csr_r, const int* __restrict__ csr_e,
    const float* __restrict__ ea, const float* __restrict__ dis,
    const float* __restrict__ bias)
{
    int w = (blockIdx.x * blockDim.x + threadIdx.x) >> 5;
    int lane = threadIdx.x & 31;
    if (w >= N_NODES * NEA) return;
    int i = w % NEA;
    int c = w / NEA;

    float dc = __ldg(&dis[i * N_NODES + c]);
    float4 acc;
    {
        float4 v = *(const float4*)(hw + (size_t)c * HC + i * HDIM + lane * 4);
        float4 b = *(const float4*)(bias + i * HDIM + lane * 4);
        float s = dc * dc;
        acc.x = b.x + s * v.x;
        acc.y = b.y + s * v.y;
        acc.z = b.z + s * v.z;
        acc.w = b.w + s * v.w;
    }

    int p0 = __ldg(&rowptr[c]);
    int p1 = __ldg(&rowptr[c + 1]);
    if (p0 < p1) {
        int r = __ldg(&csr_r[p0]);
        int e = __ldg(&csr_e[p0]);
        for (int p = p0; p < p1; p++) {
            int rn = 0, en = 0;
            if (p + 1 < p1) {
                rn = __ldg(&csr_r[p + 1]);
                en = __ldg(&csr_e[p + 1]);
            }
            float co = __ldg(&dis[i * N_NODES + r]) * dc * __ldg(&ea[(size_t)e * NEA + i]);
            float4 v = *(const float4*)(hw + (size_t)r * HC + i * HDIM + lane * 4);
            acc.x += co * v.x;
            acc.y += co * v.y;
            acc.z += co * v.z;
            acc.w += co * v.w;
            r = rn;
            e = en;
        }
    }

    acc.x = fmaxf(acc.x, 0.f);
    acc.y = fmaxf(acc.y, 0.f);
    acc.z = fmaxf(acc.z, 0.f);
    acc.w = fmaxf(acc.w, 0.f);
    size_t o = (size_t)c * HC + i * HDIM + lane * 4;
    split_store4(outH + o, outL + o, acc);
}

// ---------------- CSR scatter, single channel -> bf16 pair ----------------
__global__ __launch_bounds__(256) void scatter1_csr_kernel(
    const float* __restrict__ hw, bf16* __restrict__ outH, bf16* __restrict__ outL,
    const int* __restrict__ rowptr, const int* __restrict__ csr_r, const int* __restrict__ csr_e,
    const float* __restrict__ ewv, const float* __restrict__ dis7,
    const float* __restrict__ bias)
{
    int c = (blockIdx.x * blockDim.x + threadIdx.x) >> 5;
    int lane = threadIdx.x & 31;
    if (c >= N_NODES) return;

    float dc = __ldg(&dis7[c]);
    float4 acc;
    {
        float4 v = *(const float4*)(hw + (size_t)c * HDIM + lane * 4);
        float4 b = *(const float4*)(bias + lane * 4);
        float s = dc * dc;
        acc.x = b.x + s * v.x;
        acc.y = b.y + s * v.y;
        acc.z = b.z + s * v.z;
        acc.w = b.w + s * v.w;
    }
    int p0 = __ldg(&rowptr[c]);
    int p1 = __ldg(&rowptr[c + 1]);
    if (p0 < p1) {
        int r = __ldg(&csr_r[p0]);
        int e = __ldg(&csr_e[p0]);
        for (int p = p0; p < p1; p++) {
            int rn = 0, en = 0;
            if (p + 1 < p1) {
                rn = __ldg(&csr_r[p + 1]);
                en = __ldg(&csr_e[p + 1]);
            }
            float co = __ldg(&dis7[r]) * dc * __ldg(&ewv[e]);
            float4 v = *(const float4*)(hw + (size_t)r * HDIM + lane * 4);
            acc.x += co * v.x;
            acc.y += co * v.y;
            acc.z += co * v.z;
            acc.w += co * v.w;
            r = rn;
            e = en;
        }
    }
    acc.x = fmaxf(acc.x, 0.f);
    acc.y = fmaxf(acc.y, 0.f);
    acc.z = fmaxf(acc.z, 0.f);
    acc.w = fmaxf(acc.w, 0.f);
    size_t o = (size_t)c * HDIM + lane * 4;
    split_store4(outH + o, outL + o, acc);
}

// ---------------- link head ----------------
__global__ void build_h0_kernel(const float* __restrict__ UV,
                                const float* __restrict__ lb0, const int* __restrict__ eit,
                                bf16* __restrict__ Hh, bf16* __restrict__ Hl)
{
    size_t idx = (size_t)blockIdx.x * blockDim.x + threadIdx.x;
    if (idx >= (size_t)2 * ET_EDGES * HLDIM) return;
    int e = (int)(idx >> 7);
    int j = (int)(idx & 127);
    int a;
    int b;
    if (e < ET_EDGES) {
        a = eit[e];
        b = eit[ET_EDGES + e];
    } else {
        int e2 = e - ET_EDGES;
        a = eit[ET_EDGES + e2];
        b = eit[e2];
    }
    float v = UV[(size_t)a * 256 + j] + UV[(size_t)b * 256 + 128 + j] + lb0[j];
    v = fmaxf(v, 0.f);
    split1(v, &Hh[idx], &Hl[idx]);
}

// final layer fused with symmetric combine: warp per test edge, computes fwd+rev rows
__global__ __launch_bounds__(256) void out_combine_kernel(
    const float* __restrict__ Hm, const float* __restrict__ lw4,
    const float* __restrict__ lb4, float* __restrict__ out)
{
    int w = (blockIdx.x * blockDim.x + threadIdx.x) >> 5;
    int lane = threadIdx.x & 31;
    if (w >= ET_EDGES) return;
    const float* Hf = Hm + (size_t)w * HLDIM;
    const float* Hr = Hm + (size_t)(ET_EDGES + w) * HLDIM;
    float f0 = Hf[lane], f1 = Hf[32 + lane], f2 = Hf[64 + lane], f3 = Hf[96 + lane];
    float r0 = Hr[lane], r1 = Hr[32 + lane], r2 = Hr[64 + lane], r3 = Hr[96 + lane];
    float af[4], arr[4];
#pragma unroll
    for (int c = 0; c < 4; c++) {
        float w0 = __ldg(&lw4[lane * 4 + c]);
        float w1 = __ldg(&lw4[(lane + 32) * 4 + c]);
        float w2 = __ldg(&lw4[(lane + 64) * 4 + c]);
        float w3 = __ldg(&lw4[(lane + 96) * 4 + c]);
        af[c]  = f0 * w0 + f1 * w1 + f2 * w2 + f3 * w3;
        arr[c] = r0 * w0 + r1 * w1 + r2 * w2 + r3 * w3;
    }
#pragma unroll
    for (int off = 16; off > 0; off >>= 1) {
#pragma unroll
        for (int c = 0; c < 4; c++) {
            af[c]  += __shfl_down_sync(0xffffffffu, af[c], off);
            arr[c] += __shfl_down_sync(0xffffffffu, arr[c], off);
        }
    }
    if (lane == 0) {
#pragma unroll
        for (int c = 0; c < 4; c++) {
            int pc = (c == 1) ? 2 : ((c == 2) ? 1 : c);
            out[(size_t)w * 4 + c] = 0.5f * ((af[c] + lb4[c]) + (arr[pc] + lb4[pc]));
        }
    }
}

// ---------------- host orchestration ----------------
static inline int cdiv(size_t a, int b) { return (int)((a + b - 1) / b); }

extern "C" void kernel_launch(void* const* d_in, const int* in_sizes, int n_in,
                              void* d_out, int out_size)
{
    const float* x    = (const float*)d_in[0];
    const int*   ei   = (const int*)  d_in[1];
    const float* ea   = (const float*)d_in[2];
    const int*   eit  = (const int*)  d_in[3];
    const float* W0   = (const float*)d_in[4];
    const float* b0   = (const float*)d_in[5];
    const float* W1   = (const float*)d_in[6];
    const float* b1   = (const float*)d_in[7];
    const float* W2   = (const float*)d_in[8];
    const float* b2   = (const float*)d_in[9];
    const float* W3   = (const float*)d_in[10];
    const float* b3   = (const float*)d_in[11];
    const float* ew1  = (const float*)d_in[12];
    const float* eb1  = (const float*)d_in[13];
    const float* ew2  = (const float*)d_in[14];
    const float* eb2  = (const float*)d_in[15];
    const float* ew3  = (const float*)d_in[16];
    const float* eb3  = (const float*)d_in[17];
    const float* lw0  = (const float*)d_in[18];
    const float* lb0  = (const float*)d_in[19];
    const float* lwh  = (const float*)d_in[20];
    const float* lbh  = (const float*)d_in[21];
    const float* lw4  = (const float*)d_in[22];
    const float* lb4  = (const float*)d_in[23];
    float* out = (float*)d_out;

    float *ew, *dis, *hw, *hw128, *UV, *Hbf;
    bf16 *x1h, *x1l, *x2h, *x2l, *x3h, *x3l, *x4h, *x4l;
    bf16 *Hah, *Hal, *Hbh, *Hbl;
    bf16 *B1h, *B1l, *B2h, *B2l, *B3h, *B3l, *Buvh, *Buvl, *Blhh, *Blhl;
    int *cnt, *cursor, *rowptr, *csr_r, *csr_e;
    cudaGetSymbolAddress((void**)&ew,    g_ew);
    cudaGetSymbolAddress((void**)&dis,   g_dis);
    cudaGetSymbolAddress((void**)&hw,    g_hw);
    cudaGetSymbolAddress((void**)&hw128, g_hw128);
    cudaGetSymbolAddress((void**)&UV,    g_UV);
    cudaGetSymbolAddress((void**)&Hbf,   g_Hb_f32);
    cudaGetSymbolAddress((void**)&x1h,   g_x1h);
    cudaGetSymbolAddress((void**)&x1l,   g_x1l);
    cudaGetSymbolAddress((void**)&x2h,   g_x2h);
    cudaGetSymbolAddress((void**)&x2l,   g_x2l);
    cudaGetSymbolAddress((void**)&x3h,   g_x3h);
    cudaGetSymbolAddress((void**)&x3l,   g_x3l);
    cudaGetSymbolAddress((void**)&x4h,   g_x4h);
    cudaGetSymbolAddress((void**)&x4l,   g_x4l);
    cudaGetSymbolAddress((void**)&Hah,   g_Hah);
    cudaGetSymbolAddress((void**)&Hal,   g_Hal);
    cudaGetSymbolAddress((void**)&Hbh,   g_Hbh);
    cudaGetSymbolAddress((void**)&Hbl,   g_Hbl);
    cudaGetSymbolAddress((void**)&B1h,   g_B1h);
    cudaGetSymbolAddress((void**)&B1l,   g_B1l);
    cudaGetSymbolAddress((void**)&B2h,   g_B2h);
    cudaGetSymbolAddress((void**)&B2l,   g_B2l);
    cudaGetSymbolAddress((void**)&B3h,   g_B3h);
    cudaGetSymbolAddress((void**)&B3l,   g_B3l);
    cudaGetSymbolAddress((void**)&Buvh,  g_Buvh);
    cudaGetSymbolAddress((void**)&Buvl,  g_Buvl);
    cudaGetSymbolAddress((void**)&Blhh,  g_Blhh);
    cudaGetSymbolAddress((void**)&Blhl,  g_Blhl);
    cudaGetSymbolAddress((void**)&cnt,   g_cnt);
    cudaGetSymbolAddress((void**)&cursor,g_cursor);
    cudaGetSymbolAddress((void**)&rowptr,g_rowptr);
    cudaGetSymbolAddress((void**)&csr_r, g_csr_r);
    cudaGetSymbolAddress((void**)&csr_e, g_csr_e);

    cudaFuncSetAttribute(gemm_mma_kernel, cudaFuncAttributeMaxDynamicSharedMemorySize, MMA_SMEM);

    const int TB = 256;
    const size_t NW = (size_t)N_NODES * HC;
    const int M2 = 2 * ET_EDGES;
    const int SCAT7_GRID = cdiv((size_t)N_NODES * NEA * 32, TB);
    const int SCAT1_GRID = cdiv((size_t)N_NODES * 32, TB);
    const int GRY = cdiv(N_NODES, 128);
    const int GRY2 = cdiv(M2, 128);

    edge_mlp_kernel<<<cdiv(E_EDGES, TB), TB>>>(ea, ew1, eb1, ew2, eb2, ew3, eb3, ew, E_EDGES);

    zero_int_kernel<<<cdiv(N_NODES, TB), TB>>>(cnt, N_NODES);
    count_kernel<<<cdiv(E_EDGES, TB), TB>>>(ei, cnt, E_EDGES);
    scan_kernel<<<1, 1024>>>(cnt, rowptr, cursor);
    csr_fill_kernel<<<cdiv(E_EDGES, TB), TB>>>(ei, cursor, csr_r, csr_e, E_EDGES);

    deg_warp_kernel<<<cdiv((size_t)N_NODES * 32, TB), TB>>>(rowptr, csr_e, ea, ew, dis);

    pack_b1_kernel<<<cdiv(HDIM * HC, TB), TB>>>(W1, B1h, B1l);
    pack_b2_kernel<<<cdiv(HC * HDIM, TB), TB>>>(W2, B2h, B2l);
    pack_b3_kernel<<<cdiv((size_t)HC * HC, TB), TB>>>(W3, B3h, B3l);
    pack_buv_kernel<<<cdiv(256 * HC, TB), TB>>>(lw0, Buvh, Buvl);
    pack_blh_kernel<<<cdiv(3 * HLDIM * HLDIM, TB), TB>>>(lwh, Blhh, Blhl);

    // layer 1
    gemm_k8_kernel<<<cdiv(NW, TB), TB>>>(x, W0, hw);
    scatter7_csr_kernel<<<SCAT7_GRID, TB>>>(hw, x1h, x1l, rowptr, csr_r, csr_e, ea, dis, b0);

    // layer 2
    gemm_mma_kernel<<<dim3(1, GRY), 256, MMA_SMEM>>>(
        x1h, x1l, B1h, B1l, hw128, (bf16*)0, (bf16*)0, N_NODES, HC, HDIM, (const float*)0, 2);
    scatter1_csr_kernel<<<SCAT1_GRID, TB>>>(hw128, x2h, x2l, rowptr, csr_r, csr_e, ew,
                                            dis + NEA * N_NODES, b1);

    // layer 3
    gemm_mma_kernel<<<dim3(7, GRY), 256, MMA_SMEM>>>(
        x2h, x2l, B2h, B2l, hw, (bf16*)0, (bf16*)0, N_NODES, HDIM, HC, (const float*)0, 2);
    scatter7_csr_kernel<<<SCAT7_GRID, TB>>>(hw, x3h, x3l, rowptr, csr_r, csr_e, ea, dis, b2);

    // layer 4
    gemm_mma_kernel<<<dim3(7, GRY), 256, MMA_SMEM>>>(
        x3h, x3l, B3h, B3l, hw, (bf16*)0, (bf16*)0, N_NODES, HC, HC, (const float*)0, 2);
    scatter7_csr_kernel<<<SCAT7_GRID, TB>>>(hw, x4h, x4l, rowptr, csr_r, csr_e, ea, dis, b3);

    // link head: UV = x4 @ Wuv
    gemm_mma_kernel<<<dim3(2, GRY), 256, MMA_SMEM>>>(
        x4h, x4l, Buvh, Buvl, UV, (bf16*)0, (bf16*)0, N_NODES, HC, 256, (const float*)0, 2);

    build_h0_kernel<<<cdiv((size_t)M2 * HLDIM, TB), TB>>>(UV, lb0, eit, Hah, Hal);

    gemm_mma_kernel<<<dim3(1, GRY2), 256, MMA_SMEM>>>(
        Hah, Hal, Blhh, Blhl, (float*)0, Hbh, Hbl, M2, HLDIM, HLDIM, lbh, 1 | 4);
    gemm_mma_kernel<<<dim3(1, GRY2), 256, MMA_SMEM>>>(
        Hbh, Hbl, Blhh + HLDIM * HLDIM, Blhl + HLDIM * HLDIM, (float*)0, Hah, Hal,
        M2, HLDIM, HLDIM, lbh + HLDIM, 1 | 4);
    gemm_mma_kernel<<<dim3(1, GRY2), 256, MMA_SMEM>>>(
        Hah, Hal, Blhh + 2 * HLDIM * HLDIM, Blhl + 2 * HLDIM * HLDIM, Hbf, (bf16*)0, (bf16*)0,
        M2, HLDIM, HLDIM, lbh + 2 * HLDIM, 1 | 2);

    out_combine_kernel<<<cdiv((size_t)ET_EDGES * 32, TB), TB>>>(Hbf, lw4, lb4, out);
}